// round 1
// baseline (speedup 1.0000x reference)
#include <cuda_runtime.h>
#include <math.h>

#define BSZ   32
#define TLEN  64
#define ED    512
#define HD    512
#define G4    2048          // 4*HID
#define M2    2048          // TLEN*BSZ
#define VOC   32000

// ---------------- scratch (device globals; no allocation) ----------------
__device__ float g_xs [M2 * ED];     // gathered embeddings [ (t*32+b), e ]
__device__ float g_pre[M2 * G4];     // gate preactivations from input path
__device__ float g_y  [M2 * HD];     // layer outputs [ (t*32+b), m ]
__device__ float g_u2 [M2 * HD];     // final decoder layer outputs
// state: h0 double-buffer [2][512*32], c0 [512*32], h1 [2][...], c1
__device__ float g_state[98304];
#define OFF_H0 0
#define OFF_C0 32768
#define OFF_H1 49152
#define OFF_C1 81920

__device__ unsigned g_barc;  // spin-barrier arrive count (self-resetting)
__device__ unsigned g_bare;  // spin-barrier epoch (monotonic; used base-relative)

// ---------------- zero state ----------------
__global__ void k_zero() {
    int i = blockIdx.x * 256 + threadIdx.x;     // 96 blocks * 256 = 24576 float4
    ((float4*)g_state)[i] = make_float4(0.f, 0.f, 0.f, 0.f);
}

// ---------------- embedding gather: xs[(t*32+b)][e] = emb[token][e] -------
__global__ void k_embed(const int* __restrict__ toks, const int* __restrict__ tgt,
                        const float* __restrict__ emb, float* __restrict__ xs, int dec) {
    int row = blockIdx.x;                 // (t*32 + b)
    int t = row >> 5, b = row & 31;
    int tok;
    if (dec) tok = (t == 0) ? 1 : tgt[b * TLEN + t - 1];   // BOS shift
    else     tok = toks[b * TLEN + t];
    const float4* src = (const float4*)(emb + (size_t)tok * ED);
    float4*       dst = (float4*)(xs + (size_t)row * ED);
    dst[threadIdx.x] = src[threadIdx.x];  // 128 threads * float4 = 512
}

// ---------------- input GEMM: C[M2][G4] = X[M2][512] @ W[G4][512]^T + b ---
__global__ void k_ingemm(const float* __restrict__ X, const float* __restrict__ W,
                         const float* __restrict__ bias, float* __restrict__ C) {
    __shared__ float As[16][64];
    __shared__ float Bs[16][64];
    int tid = threadIdx.x;
    int tx = tid & 15, ty = tid >> 4;
    int rb = blockIdx.y * 64, cb = blockIdx.x * 64;
    int lr = tid >> 2, lk = (tid & 3) << 2;
    float acc[4][4] = {};
    for (int kk = 0; kk < 512; kk += 16) {
        float4 av = *(const float4*)(X + (size_t)(rb + lr) * 512 + kk + lk);
        As[lk + 0][lr] = av.x; As[lk + 1][lr] = av.y; As[lk + 2][lr] = av.z; As[lk + 3][lr] = av.w;
        float4 bv = *(const float4*)(W + (size_t)(cb + lr) * 512 + kk + lk);
        Bs[lk + 0][lr] = bv.x; Bs[lk + 1][lr] = bv.y; Bs[lk + 2][lr] = bv.z; Bs[lk + 3][lr] = bv.w;
        __syncthreads();
        #pragma unroll
        for (int k = 0; k < 16; k++) {
            float4 a = *(const float4*)(&As[k][ty * 4]);
            float4 q = *(const float4*)(&Bs[k][tx * 4]);
            float avv[4] = {a.x, a.y, a.z, a.w};
            float bvv[4] = {q.x, q.y, q.z, q.w};
            #pragma unroll
            for (int i = 0; i < 4; i++)
                #pragma unroll
                for (int j = 0; j < 4; j++)
                    acc[i][j] = fmaf(avv[i], bvv[j], acc[i][j]);
        }
        __syncthreads();
    }
    float4 bb = *(const float4*)(bias + cb + tx * 4);
    float bx[4] = {bb.x, bb.y, bb.z, bb.w};
    #pragma unroll
    for (int i = 0; i < 4; i++) {
        float4 o = make_float4(acc[i][0] + bx[0], acc[i][1] + bx[1],
                               acc[i][2] + bx[2], acc[i][3] + bx[3]);
        *(float4*)(C + (size_t)(rb + ty * 4 + i) * G4 + cb + tx * 4) = o;
    }
}

// ---------------- projection: out[b][t][v] = u2[(t*32+b)] . lin_W[v] + lin_b
__global__ void k_proj(const float* __restrict__ X, const float* __restrict__ W,
                       const float* __restrict__ bias, float* __restrict__ out) {
    __shared__ float As[16][64];
    __shared__ float Bs[16][64];
    int tid = threadIdx.x;
    int tx = tid & 15, ty = tid >> 4;
    int rb = blockIdx.y * 64, cb = blockIdx.x * 64;
    int lr = tid >> 2, lk = (tid & 3) << 2;
    float acc[4][4] = {};
    for (int kk = 0; kk < 512; kk += 16) {
        float4 av = *(const float4*)(X + (size_t)(rb + lr) * 512 + kk + lk);
        As[lk + 0][lr] = av.x; As[lk + 1][lr] = av.y; As[lk + 2][lr] = av.z; As[lk + 3][lr] = av.w;
        float4 bv = *(const float4*)(W + (size_t)(cb + lr) * 512 + kk + lk);
        Bs[lk + 0][lr] = bv.x; Bs[lk + 1][lr] = bv.y; Bs[lk + 2][lr] = bv.z; Bs[lk + 3][lr] = bv.w;
        __syncthreads();
        #pragma unroll
        for (int k = 0; k < 16; k++) {
            float4 a = *(const float4*)(&As[k][ty * 4]);
            float4 q = *(const float4*)(&Bs[k][tx * 4]);
            float avv[4] = {a.x, a.y, a.z, a.w};
            float bvv[4] = {q.x, q.y, q.z, q.w};
            #pragma unroll
            for (int i = 0; i < 4; i++)
                #pragma unroll
                for (int j = 0; j < 4; j++)
                    acc[i][j] = fmaf(avv[i], bvv[j], acc[i][j]);
        }
        __syncthreads();
    }
    float4 bb = *(const float4*)(bias + cb + tx * 4);
    float bx[4] = {bb.x, bb.y, bb.z, bb.w};
    #pragma unroll
    for (int i = 0; i < 4; i++) {
        int m = rb + ty * 4 + i;          // (t*32 + b)
        int b = m & 31, t = m >> 5;
        size_t orow = (size_t)(b * TLEN + t);
        float4 o = make_float4(acc[i][0] + bx[0], acc[i][1] + bx[1],
                               acc[i][2] + bx[2], acc[i][3] + bx[3]);
        *(float4*)(out + orow * VOC + cb + tx * 4) = o;
    }
}

// ---------------- persistent recurrence: 64 steps, 128 blocks --------------
// Block bl owns hidden dims m in [4*bl, 4*bl+4). Gate rows j = gate*512 + m.
// h in global double-buffer [2][512][32] ("[k][b]"); c lives in registers.
__global__ void k_recur(const float* __restrict__ pre, const float* __restrict__ Whh,
                        float* __restrict__ hbuf, float* __restrict__ cbuf,
                        float* __restrict__ yout) {
    extern __shared__ float h_sm[];          // 512*32 floats = 64KB
    __shared__ float g_sm[16][32];
    int tid = threadIdx.x;
    int r = tid >> 4, p = tid & 15;
    int b0 = p * 2;
    int j = (r >> 2) * 512 + blockIdx.x * 4 + (r & 3);
    const float4* wrow = (const float4*)(Whh + (size_t)j * 512);

    unsigned base = 0;
    if (tid == 0) base = *(volatile unsigned*)&g_bare;

    int em  = tid < 128;
    int m_l = (tid >> 5) & 3, eb = tid & 31;
    int m_g = blockIdx.x * 4 + m_l;
    float c_reg = 0.f;
    if (em) c_reg = cbuf[m_g * 32 + eb];
    __syncthreads();

    for (int t = 0; t < TLEN; t++) {
        // fill h_sm from the read buffer (bypass L1: other SMs wrote it)
        const float4* hsrc = (const float4*)(hbuf + (t & 1) * 16384);
        #pragma unroll
        for (int i = 0; i < 16; i++)
            ((float4*)h_sm)[tid + i * 256] = __ldcg(hsrc + tid + i * 256);
        __syncthreads();

        float acc0 = pre[(size_t)(t * 32 + b0)     * G4 + j];
        float acc1 = pre[(size_t)(t * 32 + b0 + 1) * G4 + j];
        #pragma unroll 8
        for (int k4 = 0; k4 < 128; k4++) {
            float4 w = wrow[k4];
            int kb = k4 * 128 + b0;
            float2 h0 = *(const float2*)(h_sm + kb);
            float2 h1 = *(const float2*)(h_sm + kb + 32);
            float2 h2 = *(const float2*)(h_sm + kb + 64);
            float2 h3 = *(const float2*)(h_sm + kb + 96);
            acc0 = fmaf(w.x, h0.x, acc0); acc1 = fmaf(w.x, h0.y, acc1);
            acc0 = fmaf(w.y, h1.x, acc0); acc1 = fmaf(w.y, h1.y, acc1);
            acc0 = fmaf(w.z, h2.x, acc0); acc1 = fmaf(w.z, h2.y, acc1);
            acc0 = fmaf(w.w, h3.x, acc0); acc1 = fmaf(w.w, h3.y, acc1);
        }
        *(float2*)(&g_sm[r][b0]) = make_float2(acc0, acc1);
        __syncthreads();

        if (em) {
            float iv = g_sm[m_l][eb];
            float fv = g_sm[4  + m_l][eb];
            float gv = g_sm[8  + m_l][eb];
            float ov = g_sm[12 + m_l][eb];
            float si = 1.f / (1.f + expf(-iv));
            float sf = 1.f / (1.f + expf(-fv));
            float so = 1.f / (1.f + expf(-ov));
            c_reg = sf * c_reg + si * tanhf(gv);
            float h = so * tanhf(c_reg);
            hbuf[((t + 1) & 1) * 16384 + m_g * 32 + eb] = h;
            yout[(size_t)(t * 32 + eb) * HD + m_g] = h;
        }
        __threadfence();     // publish h writes to L2 before barrier arrive
        __syncthreads();

        if (tid == 0) {
            unsigned old = atomicAdd(&g_barc, 1);
            if (old == gridDim.x - 1) {
                atomicExch(&g_barc, 0);
                __threadfence();
                atomicAdd(&g_bare, 1);
            } else {
                while ((*(volatile unsigned*)&g_bare) - base < (unsigned)(t + 1)) {}
            }
            __threadfence();
        }
        __syncthreads();
    }
    if (em) cbuf[m_g * 32 + eb] = c_reg;
}

// ---------------- launcher ----------------
extern "C" void kernel_launch(void* const* d_in, const int* in_sizes, int n_in,
                              void* d_out, int out_size) {
    const int*   x       = (const int*)  d_in[0];
    const int*   tgt     = (const int*)  d_in[1];
    const float* enc_emb = (const float*)d_in[2];
    const float* dec_emb = (const float*)d_in[3];
    const float* e0_Wih  = (const float*)d_in[4];
    const float* e0_Whh  = (const float*)d_in[5];
    const float* e0_b    = (const float*)d_in[6];
    const float* e1_Wih  = (const float*)d_in[7];
    const float* e1_Whh  = (const float*)d_in[8];
    const float* e1_b    = (const float*)d_in[9];
    const float* d0_Wih  = (const float*)d_in[10];
    const float* d0_Whh  = (const float*)d_in[11];
    const float* d0_b    = (const float*)d_in[12];
    const float* d1_Wih  = (const float*)d_in[13];
    const float* d1_Whh  = (const float*)d_in[14];
    const float* d1_b    = (const float*)d_in[15];
    const float* lin_W   = (const float*)d_in[16];
    const float* lin_b   = (const float*)d_in[17];
    float* out = (float*)d_out;

    float *xs, *pre, *y, *u2, *st;
    cudaGetSymbolAddress((void**)&xs,  g_xs);
    cudaGetSymbolAddress((void**)&pre, g_pre);
    cudaGetSymbolAddress((void**)&y,   g_y);
    cudaGetSymbolAddress((void**)&u2,  g_u2);
    cudaGetSymbolAddress((void**)&st,  g_state);

    cudaFuncSetAttribute(k_recur, cudaFuncAttributeMaxDynamicSharedMemorySize, 65536);

    dim3 gg(32, 32), gp(VOC / 64, 32);

    k_zero<<<96, 256>>>();

    // encoder
    k_embed<<<M2, 128>>>(x, tgt, enc_emb, xs, 0);
    k_ingemm<<<gg, 256>>>(xs, e0_Wih, e0_b, pre);
    k_recur<<<128, 256, 65536>>>(pre, e0_Whh, st + OFF_H0, st + OFF_C0, y);
    k_ingemm<<<gg, 256>>>(y, e1_Wih, e1_b, pre);
    k_recur<<<128, 256, 65536>>>(pre, e1_Whh, st + OFF_H1, st + OFF_C1, u2); // y unused

    // decoder (teacher forcing: inputs known upfront)
    k_embed<<<M2, 128>>>(x, tgt, dec_emb, xs, 1);
    k_ingemm<<<gg, 256>>>(xs, d0_Wih, d0_b, pre);
    k_recur<<<128, 256, 65536>>>(pre, d0_Whh, st + OFF_H0, st + OFF_C0, y);  // u1
    k_ingemm<<<gg, 256>>>(y, d1_Wih, d1_b, pre);
    k_recur<<<128, 256, 65536>>>(pre, d1_Whh, st + OFF_H1, st + OFF_C1, u2); // u2

    k_proj<<<gp, 256>>>(u2, lin_W, lin_b, out);
}

// round 3
// speedup vs baseline: 1.3045x; 1.3045x over previous
#include <cuda_runtime.h>
#include <cuda_bf16.h>
#include <math.h>
#include <stdint.h>

#define BSZ   32
#define TLEN  64
#define ED    512
#define HD    512
#define G4    2048
#define M2    2048
#define VOC   32000

// ---------------- scratch (device globals; no allocation) ----------------
__device__ float g_xs [M2 * ED];
__device__ float g_pre[M2 * G4];
__device__ float g_y  [M2 * HD];
__device__ float g_u2 [M2 * HD];
__device__ float g_state[98304];
#define OFF_H0 0
#define OFF_C0 32768
#define OFF_H1 49152
#define OFF_C1 81920

__device__ unsigned g_barc;
__device__ unsigned g_bare;

// ================= helpers =================
__device__ __forceinline__ uint32_t smem_u32(const void* p) {
    uint32_t a;
    asm("{ .reg .u64 t; cvta.to.shared.u64 t, %1; cvt.u32.u64 %0, t; }" : "=r"(a) : "l"(p));
    return a;
}

#define LDMX4(r0, r1, r2, r3, a) \
    asm volatile("ldmatrix.sync.aligned.m8n8.x4.shared.b16 {%0,%1,%2,%3}, [%4];" \
        : "=r"(r0), "=r"(r1), "=r"(r2), "=r"(r3) : "r"(a))

#define STS128(a, r0, r1, r2, r3) \
    asm volatile("st.shared.v4.b32 [%0], {%1,%2,%3,%4};" \
        :: "r"(a), "r"(r0), "r"(r1), "r"(r2), "r"(r3) : "memory")

__device__ __forceinline__ void mma16816(float* d, const uint32_t* a, const uint32_t* b) {
    asm volatile("mma.sync.aligned.m16n8k16.row.col.f32.bf16.bf16.f32 "
        "{%0,%1,%2,%3},{%4,%5,%6,%7},{%8,%9},{%0,%1,%2,%3};"
        : "+f"(d[0]), "+f"(d[1]), "+f"(d[2]), "+f"(d[3])
        : "r"(a[0]), "r"(a[1]), "r"(a[2]), "r"(a[3]), "r"(b[0]), "r"(b[1]));
}

// fp32x16 -> bf16 hi (8 b32) + bf16 lo residual (8 b32)
__device__ __forceinline__ void cvt_hilo(const float4* v, uint32_t* h, uint32_t* l) {
    #pragma unroll
    for (int i = 0; i < 4; i++) {
        float a0 = v[i].x, a1 = v[i].y, a2 = v[i].z, a3 = v[i].w;
        uint32_t h0, h1, l0, l1;
        asm("cvt.rn.bf16x2.f32 %0, %1, %2;" : "=r"(h0) : "f"(a1), "f"(a0));
        asm("cvt.rn.bf16x2.f32 %0, %1, %2;" : "=r"(h1) : "f"(a3), "f"(a2));
        float r0 = a0 - __uint_as_float(h0 << 16);
        float r1 = a1 - __uint_as_float(h0 & 0xFFFF0000u);
        float r2 = a2 - __uint_as_float(h1 << 16);
        float r3 = a3 - __uint_as_float(h1 & 0xFFFF0000u);
        asm("cvt.rn.bf16x2.f32 %0, %1, %2;" : "=r"(l0) : "f"(r1), "f"(r0));
        asm("cvt.rn.bf16x2.f32 %0, %1, %2;" : "=r"(l1) : "f"(r3), "f"(r2));
        h[2*i] = h0; h[2*i+1] = h1; l[2*i] = l0; l[2*i+1] = l1;
    }
}

// ================= split-bf16 HMMA GEMM =================
// C[M][N] = X[M,512] @ W[N,512]^T + bias ; PERM=1 permutes output rows for proj.
#define PADK   40                     // bf16 per smem row (80B stride, conflict-free)
#define T_AH   0
#define T_AL   10240
#define T_BH   20480
#define T_BL   30720
#define STAGE  40960
#define GSMEM  81920

__device__ __forceinline__ void stage_store(uint32_t base, const float4* v) {
    uint32_t h[8], l[8];
    cvt_hilo(v, h, l);
    STS128(base,           h[0], h[1], h[2], h[3]);
    STS128(base + 16,      h[4], h[5], h[6], h[7]);
    STS128(base + 10240,      l[0], l[1], l[2], l[3]);
    STS128(base + 10240 + 16, l[4], l[5], l[6], l[7]);
}

template<int PERM>
__global__ void __launch_bounds__(256, 1)
k_mmagemm(const float* __restrict__ X, const float* __restrict__ W,
          const float* __restrict__ bias, float* __restrict__ C, int ldc) {
    extern __shared__ char smx[];
    uint32_t sb = smem_u32(smx);
    int tid = threadIdx.x, lid = tid & 31, wid = tid >> 5;
    int wm = wid >> 2, wn = wid & 3;
    int rb = blockIdx.x * 128, cb = blockIdx.y * 128;

    // staging: thread handles row r, k-halves of 16 floats
    int r = tid >> 1, kh = (tid & 1) * 16;
    const float4* xp = (const float4*)(X + (size_t)(rb + r) * 512 + kh);
    const float4* wp = (const float4*)(W + (size_t)(cb + r) * 512 + kh);
    uint32_t stb = sb + (uint32_t)(r * PADK + kh) * 2;

    float4 xr[4], wr[4];
    #pragma unroll
    for (int i = 0; i < 4; i++) { xr[i] = xp[i]; wr[i] = wp[i]; }
    stage_store(stb + T_AH, xr);
    stage_store(stb + T_BH, wr);
    __syncthreads();

    uint32_t abase = sb + (uint32_t)((wm * 64 + (lid & 15)) * PADK + (lid >> 4) * 8) * 2;
    uint32_t bbase = sb + T_BH + (uint32_t)((wn * 32 + (lid & 15)) * PADK + (lid >> 4) * 8) * 2;

    float acc[4][4][4] = {};

    for (int c = 0; c < 16; c++) {
        if (c < 15) {
            #pragma unroll
            for (int i = 0; i < 4; i++) { xr[i] = xp[(c + 1) * 8 + i]; wr[i] = wp[(c + 1) * 8 + i]; }
        }
        uint32_t so = (uint32_t)(c & 1) * STAGE;
        #pragma unroll
        for (int ks = 0; ks < 2; ks++) {
            uint32_t ah[4][4], al[4][4], bh[4][2], bl[4][2];
            #pragma unroll
            for (int ma = 0; ma < 4; ma++) {
                uint32_t ad = abase + so + (uint32_t)(ma * 16 * PADK * 2 + ks * 32);
                LDMX4(ah[ma][0], ah[ma][1], ah[ma][2], ah[ma][3], ad);
                LDMX4(al[ma][0], al[ma][1], al[ma][2], al[ma][3], ad + 10240);
            }
            #pragma unroll
            for (int p = 0; p < 2; p++) {
                uint32_t bd = bbase + so + (uint32_t)(p * 16 * PADK * 2 + ks * 32);
                uint32_t m0, m1, m2, m3;
                LDMX4(m0, m1, m2, m3, bd);
                bh[2*p][0] = m0; bh[2*p][1] = m2; bh[2*p+1][0] = m1; bh[2*p+1][1] = m3;
                LDMX4(m0, m1, m2, m3, bd + 10240);
                bl[2*p][0] = m0; bl[2*p][1] = m2; bl[2*p+1][0] = m1; bl[2*p+1][1] = m3;
            }
            #pragma unroll
            for (int ma = 0; ma < 4; ma++)
                #pragma unroll
                for (int na = 0; na < 4; na++) {
                    mma16816(acc[ma][na], ah[ma], bh[na]);
                    mma16816(acc[ma][na], ah[ma], bl[na]);
                    mma16816(acc[ma][na], al[ma], bh[na]);
                }
        }
        if (c < 15) {
            uint32_t st2 = stb + (uint32_t)((c + 1) & 1) * STAGE;
            stage_store(st2 + T_AH, xr);
            stage_store(st2 + T_BH, wr);
        }
        __syncthreads();
    }

    // epilogue: d0,d1 -> row m, cols c0..c0+1 ; d2,d3 -> row m+8
    #pragma unroll
    for (int ma = 0; ma < 4; ma++) {
        int m  = rb + wm * 64 + ma * 16 + (lid >> 2);
        int m2 = m + 8;
        size_t ro0 = PERM ? (size_t)((m  & 31) * TLEN + (m  >> 5)) : (size_t)m;
        size_t ro1 = PERM ? (size_t)((m2 & 31) * TLEN + (m2 >> 5)) : (size_t)m2;
        #pragma unroll
        for (int na = 0; na < 4; na++) {
            int c0 = cb + wn * 32 + na * 8 + (lid & 3) * 2;
            float2 bv = *(const float2*)(bias + c0);
            float* a = acc[ma][na];
            *(float2*)(C + ro0 * (size_t)ldc + c0) = make_float2(a[0] + bv.x, a[1] + bv.y);
            *(float2*)(C + ro1 * (size_t)ldc + c0) = make_float2(a[2] + bv.x, a[3] + bv.y);
        }
    }
}

// ---------------- zero state ----------------
__global__ void k_zero() {
    int i = blockIdx.x * 256 + threadIdx.x;
    ((float4*)g_state)[i] = make_float4(0.f, 0.f, 0.f, 0.f);
}

// ---------------- embedding gather ----------------
__global__ void k_embed(const int* __restrict__ toks, const int* __restrict__ tgt,
                        const float* __restrict__ emb, float* __restrict__ xs, int dec) {
    int row = blockIdx.x;
    int t = row >> 5, b = row & 31;
    int tok;
    if (dec) tok = (t == 0) ? 1 : tgt[b * TLEN + t - 1];
    else     tok = toks[b * TLEN + t];
    const float4* src = (const float4*)(emb + (size_t)tok * ED);
    float4*       dst = (float4*)(xs + (size_t)row * ED);
    dst[threadIdx.x] = src[threadIdx.x];
}

// ---------------- persistent recurrence (unchanged, known-good) ----------
__global__ void k_recur(const float* __restrict__ pre, const float* __restrict__ Whh,
                        float* __restrict__ hbuf, float* __restrict__ cbuf,
                        float* __restrict__ yout) {
    extern __shared__ float h_sm[];
    __shared__ float g_sm[16][32];
    int tid = threadIdx.x;
    int r = tid >> 4, p = tid & 15;
    int b0 = p * 2;
    int j = (r >> 2) * 512 + blockIdx.x * 4 + (r & 3);
    const float4* wrow = (const float4*)(Whh + (size_t)j * 512);

    unsigned base = 0;
    if (tid == 0) base = *(volatile unsigned*)&g_bare;

    int em  = tid < 128;
    int m_l = (tid >> 5) & 3, eb = tid & 31;
    int m_g = blockIdx.x * 4 + m_l;
    float c_reg = 0.f;
    if (em) c_reg = cbuf[m_g * 32 + eb];
    __syncthreads();

    for (int t = 0; t < TLEN; t++) {
        const float4* hsrc = (const float4*)(hbuf + (t & 1) * 16384);
        #pragma unroll
        for (int i = 0; i < 16; i++)
            ((float4*)h_sm)[tid + i * 256] = __ldcg(hsrc + tid + i * 256);
        __syncthreads();

        float acc0 = pre[(size_t)(t * 32 + b0)     * G4 + j];
        float acc1 = pre[(size_t)(t * 32 + b0 + 1) * G4 + j];
        #pragma unroll 8
        for (int k4 = 0; k4 < 128; k4++) {
            float4 w = wrow[k4];
            int kb = k4 * 128 + b0;
            float2 h0 = *(const float2*)(h_sm + kb);
            float2 h1 = *(const float2*)(h_sm + kb + 32);
            float2 h2 = *(const float2*)(h_sm + kb + 64);
            float2 h3 = *(const float2*)(h_sm + kb + 96);
            acc0 = fmaf(w.x, h0.x, acc0); acc1 = fmaf(w.x, h0.y, acc1);
            acc0 = fmaf(w.y, h1.x, acc0); acc1 = fmaf(w.y, h1.y, acc1);
            acc0 = fmaf(w.z, h2.x, acc0); acc1 = fmaf(w.z, h2.y, acc1);
            acc0 = fmaf(w.w, h3.x, acc0); acc1 = fmaf(w.w, h3.y, acc1);
        }
        *(float2*)(&g_sm[r][b0]) = make_float2(acc0, acc1);
        __syncthreads();

        if (em) {
            float iv = g_sm[m_l][eb];
            float fv = g_sm[4  + m_l][eb];
            float gv = g_sm[8  + m_l][eb];
            float ov = g_sm[12 + m_l][eb];
            float si = 1.f / (1.f + expf(-iv));
            float sf = 1.f / (1.f + expf(-fv));
            float so = 1.f / (1.f + expf(-ov));
            c_reg = sf * c_reg + si * tanhf(gv);
            float h = so * tanhf(c_reg);
            hbuf[((t + 1) & 1) * 16384 + m_g * 32 + eb] = h;
            yout[(size_t)(t * 32 + eb) * HD + m_g] = h;
        }
        __threadfence();
        __syncthreads();

        if (tid == 0) {
            unsigned old = atomicAdd(&g_barc, 1);
            if (old == gridDim.x - 1) {
                atomicExch(&g_barc, 0);
                __threadfence();
                atomicAdd(&g_bare, 1);
            } else {
                while ((*(volatile unsigned*)&g_bare) - base < (unsigned)(t + 1)) {}
            }
            __threadfence();
        }
        __syncthreads();
    }
    if (em) cbuf[m_g * 32 + eb] = c_reg;
}

// ---------------- launcher ----------------
extern "C" void kernel_launch(void* const* d_in, const int* in_sizes, int n_in,
                              void* d_out, int out_size) {
    const int*   x       = (const int*)  d_in[0];
    const int*   tgt     = (const int*)  d_in[1];
    const float* enc_emb = (const float*)d_in[2];
    const float* dec_emb = (const float*)d_in[3];
    const float* e0_Wih  = (const float*)d_in[4];
    const float* e0_Whh  = (const float*)d_in[5];
    const float* e0_b    = (const float*)d_in[6];
    const float* e1_Wih  = (const float*)d_in[7];
    const float* e1_Whh  = (const float*)d_in[8];
    const float* e1_b    = (const float*)d_in[9];
    const float* d0_Wih  = (const float*)d_in[10];
    const float* d0_Whh  = (const float*)d_in[11];
    const float* d0_b    = (const float*)d_in[12];
    const float* d1_Wih  = (const float*)d_in[13];
    const float* d1_Whh  = (const float*)d_in[14];
    const float* d1_b    = (const float*)d_in[15];
    const float* lin_W   = (const float*)d_in[16];
    const float* lin_b   = (const float*)d_in[17];
    float* out = (float*)d_out;

    float *xs, *pre, *y, *u2, *st;
    cudaGetSymbolAddress((void**)&xs,  g_xs);
    cudaGetSymbolAddress((void**)&pre, g_pre);
    cudaGetSymbolAddress((void**)&y,   g_y);
    cudaGetSymbolAddress((void**)&u2,  g_u2);
    cudaGetSymbolAddress((void**)&st,  g_state);

    cudaFuncSetAttribute(k_recur, cudaFuncAttributeMaxDynamicSharedMemorySize, 65536);
    cudaFuncSetAttribute(k_mmagemm<0>, cudaFuncAttributeMaxDynamicSharedMemorySize, GSMEM);
    cudaFuncSetAttribute(k_mmagemm<1>, cudaFuncAttributeMaxDynamicSharedMemorySize, GSMEM);

    dim3 gg(16, 16), gp(16, VOC / 128);

    k_zero<<<96, 256>>>();

    // encoder
    k_embed<<<M2, 128>>>(x, tgt, enc_emb, xs, 0);
    k_mmagemm<0><<<gg, 256, GSMEM>>>(xs, e0_Wih, e0_b, pre, G4);
    k_recur<<<128, 256, 65536>>>(pre, e0_Whh, st + OFF_H0, st + OFF_C0, y);
    k_mmagemm<0><<<gg, 256, GSMEM>>>(y, e1_Wih, e1_b, pre, G4);
    k_recur<<<128, 256, 65536>>>(pre, e1_Whh, st + OFF_H1, st + OFF_C1, u2);

    // decoder
    k_embed<<<M2, 128>>>(x, tgt, dec_emb, xs, 1);
    k_mmagemm<0><<<gg, 256, GSMEM>>>(xs, d0_Wih, d0_b, pre, G4);
    k_recur<<<128, 256, 65536>>>(pre, d0_Whh, st + OFF_H0, st + OFF_C0, y);
    k_mmagemm<0><<<gg, 256, GSMEM>>>(y, d1_Wih, d1_b, pre, G4);
    k_recur<<<128, 256, 65536>>>(pre, d1_Whh, st + OFF_H1, st + OFF_C1, u2);

    // projection (HMMA split-bf16, permuted output rows)
    k_mmagemm<1><<<gp, 256, GSMEM>>>(u2, lin_W, lin_b, out, VOC);
}

// round 4
// speedup vs baseline: 1.3675x; 1.0483x over previous
#include <cuda_runtime.h>
#include <cuda_bf16.h>
#include <math.h>
#include <stdint.h>

#define BSZ   32
#define TLEN  64
#define ED    512
#define HD    512
#define G4    2048
#define M2    2048
#define VOC   32000
#define RB    128          // recurrence blocks

// ---------------- scratch (device globals; no allocation) ----------------
__device__ float g_xs [M2 * ED];
__device__ float g_pre[M2 * G4];
__device__ float g_y  [M2 * HD];
__device__ float g_u2 [M2 * HD];
__device__ float g_state[98304];
#define OFF_H0 0
#define OFF_C0 32768
#define OFF_H1 49152
#define OFF_C1 81920

__device__ unsigned g_flags[RB];   // monotonic per-block step counters

// ================= helpers =================
__device__ __forceinline__ uint32_t smem_u32(const void* p) {
    uint32_t a;
    asm("{ .reg .u64 t; cvta.to.shared.u64 t, %1; cvt.u32.u64 %0, t; }" : "=r"(a) : "l"(p));
    return a;
}

#define LDMX4(r0, r1, r2, r3, a) \
    asm volatile("ldmatrix.sync.aligned.m8n8.x4.shared.b16 {%0,%1,%2,%3}, [%4];" \
        : "=r"(r0), "=r"(r1), "=r"(r2), "=r"(r3) : "r"(a))

#define STS128(a, r0, r1, r2, r3) \
    asm volatile("st.shared.v4.b32 [%0], {%1,%2,%3,%4};" \
        :: "r"(a), "r"(r0), "r"(r1), "r"(r2), "r"(r3) : "memory")

__device__ __forceinline__ void mma16816(float* d, const uint32_t* a, const uint32_t* b) {
    asm volatile("mma.sync.aligned.m16n8k16.row.col.f32.bf16.bf16.f32 "
        "{%0,%1,%2,%3},{%4,%5,%6,%7},{%8,%9},{%0,%1,%2,%3};"
        : "+f"(d[0]), "+f"(d[1]), "+f"(d[2]), "+f"(d[3])
        : "r"(a[0]), "r"(a[1]), "r"(a[2]), "r"(a[3]), "r"(b[0]), "r"(b[1]));
}

__device__ __forceinline__ void cvt_hilo(const float4* v, uint32_t* h, uint32_t* l) {
    #pragma unroll
    for (int i = 0; i < 4; i++) {
        float a0 = v[i].x, a1 = v[i].y, a2 = v[i].z, a3 = v[i].w;
        uint32_t h0, h1, l0, l1;
        asm("cvt.rn.bf16x2.f32 %0, %1, %2;" : "=r"(h0) : "f"(a1), "f"(a0));
        asm("cvt.rn.bf16x2.f32 %0, %1, %2;" : "=r"(h1) : "f"(a3), "f"(a2));
        float r0 = a0 - __uint_as_float(h0 << 16);
        float r1 = a1 - __uint_as_float(h0 & 0xFFFF0000u);
        float r2 = a2 - __uint_as_float(h1 << 16);
        float r3 = a3 - __uint_as_float(h1 & 0xFFFF0000u);
        asm("cvt.rn.bf16x2.f32 %0, %1, %2;" : "=r"(l0) : "f"(r1), "f"(r0));
        asm("cvt.rn.bf16x2.f32 %0, %1, %2;" : "=r"(l1) : "f"(r3), "f"(r2));
        h[2*i] = h0; h[2*i+1] = h1; l[2*i] = l0; l[2*i+1] = l1;
    }
}

// ================= split-bf16 HMMA GEMM (unchanged from R3, known-good) ====
#define PADK   40
#define T_BH   20480
#define STAGE  40960
#define GSMEM  81920

__device__ __forceinline__ void stage_store(uint32_t base, const float4* v) {
    uint32_t h[8], l[8];
    cvt_hilo(v, h, l);
    STS128(base,              h[0], h[1], h[2], h[3]);
    STS128(base + 16,         h[4], h[5], h[6], h[7]);
    STS128(base + 10240,      l[0], l[1], l[2], l[3]);
    STS128(base + 10240 + 16, l[4], l[5], l[6], l[7]);
}

template<int PERM>
__global__ void __launch_bounds__(256, 1)
k_mmagemm(const float* __restrict__ X, const float* __restrict__ W,
          const float* __restrict__ bias, float* __restrict__ C, int ldc) {
    extern __shared__ char smx[];
    uint32_t sb = smem_u32(smx);
    int tid = threadIdx.x, lid = tid & 31, wid = tid >> 5;
    int wm = wid >> 2, wn = wid & 3;
    int rb = blockIdx.x * 128, cb = blockIdx.y * 128;

    int r = tid >> 1, kh = (tid & 1) * 16;
    const float4* xp = (const float4*)(X + (size_t)(rb + r) * 512 + kh);
    const float4* wp = (const float4*)(W + (size_t)(cb + r) * 512 + kh);
    uint32_t stb = sb + (uint32_t)(r * PADK + kh) * 2;

    float4 xr[4], wr[4];
    #pragma unroll
    for (int i = 0; i < 4; i++) { xr[i] = xp[i]; wr[i] = wp[i]; }
    stage_store(stb, xr);
    stage_store(stb + T_BH, wr);
    __syncthreads();

    uint32_t abase = sb + (uint32_t)((wm * 64 + (lid & 15)) * PADK + (lid >> 4) * 8) * 2;
    uint32_t bbase = sb + T_BH + (uint32_t)((wn * 32 + (lid & 15)) * PADK + (lid >> 4) * 8) * 2;

    float acc[4][4][4] = {};

    for (int c = 0; c < 16; c++) {
        if (c < 15) {
            #pragma unroll
            for (int i = 0; i < 4; i++) { xr[i] = xp[(c + 1) * 8 + i]; wr[i] = wp[(c + 1) * 8 + i]; }
        }
        uint32_t so = (uint32_t)(c & 1) * STAGE;
        #pragma unroll
        for (int ks = 0; ks < 2; ks++) {
            uint32_t ah[4][4], al[4][4], bh[4][2], bl[4][2];
            #pragma unroll
            for (int ma = 0; ma < 4; ma++) {
                uint32_t ad = abase + so + (uint32_t)(ma * 16 * PADK * 2 + ks * 32);
                LDMX4(ah[ma][0], ah[ma][1], ah[ma][2], ah[ma][3], ad);
                LDMX4(al[ma][0], al[ma][1], al[ma][2], al[ma][3], ad + 10240);
            }
            #pragma unroll
            for (int p = 0; p < 2; p++) {
                uint32_t bd = bbase + so + (uint32_t)(p * 16 * PADK * 2 + ks * 32);
                uint32_t m0, m1, m2, m3;
                LDMX4(m0, m1, m2, m3, bd);
                bh[2*p][0] = m0; bh[2*p][1] = m2; bh[2*p+1][0] = m1; bh[2*p+1][1] = m3;
                LDMX4(m0, m1, m2, m3, bd + 10240);
                bl[2*p][0] = m0; bl[2*p][1] = m2; bl[2*p+1][0] = m1; bl[2*p+1][1] = m3;
            }
            #pragma unroll
            for (int ma = 0; ma < 4; ma++)
                #pragma unroll
                for (int na = 0; na < 4; na++) {
                    mma16816(acc[ma][na], ah[ma], bh[na]);
                    mma16816(acc[ma][na], ah[ma], bl[na]);
                    mma16816(acc[ma][na], al[ma], bh[na]);
                }
        }
        if (c < 15) {
            uint32_t st2 = stb + (uint32_t)((c + 1) & 1) * STAGE;
            stage_store(st2, xr);
            stage_store(st2 + T_BH, wr);
        }
        __syncthreads();
    }

    #pragma unroll
    for (int ma = 0; ma < 4; ma++) {
        int m  = rb + wm * 64 + ma * 16 + (lid >> 2);
        int m2 = m + 8;
        size_t ro0 = PERM ? (size_t)((m  & 31) * TLEN + (m  >> 5)) : (size_t)m;
        size_t ro1 = PERM ? (size_t)((m2 & 31) * TLEN + (m2 >> 5)) : (size_t)m2;
        #pragma unroll
        for (int na = 0; na < 4; na++) {
            int c0 = cb + wn * 32 + na * 8 + (lid & 3) * 2;
            float2 bv = *(const float2*)(bias + c0);
            float* a = acc[ma][na];
            *(float2*)(C + ro0 * (size_t)ldc + c0) = make_float2(a[0] + bv.x, a[1] + bv.y);
            *(float2*)(C + ro1 * (size_t)ldc + c0) = make_float2(a[2] + bv.x, a[3] + bv.y);
        }
    }
}

// ---------------- zero state ----------------
__global__ void k_zero() {
    int i = blockIdx.x * 256 + threadIdx.x;
    ((float4*)g_state)[i] = make_float4(0.f, 0.f, 0.f, 0.f);
}

// ---------------- embedding gather ----------------
__global__ void k_embed(const int* __restrict__ toks, const int* __restrict__ tgt,
                        const float* __restrict__ emb, float* __restrict__ xs, int dec) {
    int row = blockIdx.x;
    int t = row >> 5, b = row & 31;
    int tok;
    if (dec) tok = (t == 0) ? 1 : tgt[b * TLEN + t - 1];
    else     tok = toks[b * TLEN + t];
    const float4* src = (const float4*)(emb + (size_t)tok * ED);
    float4*       dst = (float4*)(xs + (size_t)row * ED);
    dst[threadIdx.x] = src[threadIdx.x];
}

// ================= persistent recurrence v2 =================
// 128 blocks; block owns 16 gate rows (4 gates x 4 m). Whh slice cached in
// smem once. h staged per step as float2 batch-pairs [p][k], stride 514 pairs
// (conflict-free LDS.128). Flag-array barrier, one fence per block per side.
#define HSTR  514
#define RSMEM ((8192 + 16448 + 512) * 4)   // w(32KB) + h(64.25KB+pad) + gates

__global__ void __launch_bounds__(256, 1)
k_recur(const float* __restrict__ pre, const float* __restrict__ Whh,
        float* __restrict__ hbuf, float* __restrict__ cbuf,
        float* __restrict__ yout) {
    extern __shared__ float sm[];
    float*  w_sm    = sm;                       // [16][512]
    float2* h_sm    = (float2*)(sm + 8192);     // [16][HSTR]
    float*  gate_sm = sm + 8192 + 16448;        // [16][32]

    int tid = threadIdx.x, bl = blockIdx.x;
    int r = tid >> 4, p = tid & 15, b0 = p * 2;
    int j = (r >> 2) * 512 + bl * 4 + (r & 3);

    // cache Whh slice once: w_sm[row][k]
    for (int i = tid; i < 2048; i += 256) {      // 2048 float4
        int row = i >> 7, kc = i & 127;
        int jj = (row >> 2) * 512 + bl * 4 + (row & 3);
        ((float4*)w_sm)[row * 128 + kc] = ((const float4*)(Whh + (size_t)jj * 512))[kc];
    }

    unsigned base = 0;
    if (tid < 32) base = *((volatile unsigned*)&g_flags[bl]);

    int em = tid < 128;
    int m_l = (tid >> 5) & 3, eb = tid & 31;
    int m_g = bl * 4 + m_l;
    float c_reg = em ? cbuf[m_g * 32 + eb] : 0.f;
    __syncthreads();

    const float4* wv = (const float4*)(w_sm + r * 512);
    const float4* hv = (const float4*)(h_sm + p * HSTR);

    for (int t = 0; t < TLEN; t++) {
        // stage h(t): coalesced LDG.128 from hbuf[t&1][k][b], scatter to [p][k] pairs
        const float4* hsrc = (const float4*)(hbuf + (t & 1) * 16384);
        #pragma unroll
        for (int i = 0; i < 16; i++) {
            int lin = tid + i * 256;             // float4 index over [512][32]
            float4 v = __ldcg(hsrc + lin);
            int k = lin >> 3;
            int pq = (lin & 7) * 2;
            h_sm[pq * HSTR + k]       = make_float2(v.x, v.y);
            h_sm[(pq + 1) * HSTR + k] = make_float2(v.z, v.w);
        }
        __syncthreads();

        float acc0 = pre[(size_t)(t * 32 + b0)     * G4 + j];
        float acc1 = pre[(size_t)(t * 32 + b0 + 1) * G4 + j];
        #pragma unroll 8
        for (int k4 = 0; k4 < 128; k4++) {
            float4 w  = wv[k4];
            float4 hA = hv[k4 * 2];
            float4 hB = hv[k4 * 2 + 1];
            acc0 = fmaf(w.x, hA.x, acc0); acc1 = fmaf(w.x, hA.y, acc1);
            acc0 = fmaf(w.y, hA.z, acc0); acc1 = fmaf(w.y, hA.w, acc1);
            acc0 = fmaf(w.z, hB.x, acc0); acc1 = fmaf(w.z, hB.y, acc1);
            acc0 = fmaf(w.w, hB.z, acc0); acc1 = fmaf(w.w, hB.w, acc1);
        }
        *(float2*)(gate_sm + r * 32 + b0) = make_float2(acc0, acc1);
        __syncthreads();

        if (em) {
            float iv = gate_sm[(0 + m_l) * 32 + eb];
            float fv = gate_sm[(4 + m_l) * 32 + eb];
            float gv = gate_sm[(8 + m_l) * 32 + eb];
            float ov = gate_sm[(12 + m_l) * 32 + eb];
            float si = 1.f / (1.f + expf(-iv));
            float sf = 1.f / (1.f + expf(-fv));
            float so = 1.f / (1.f + expf(-ov));
            c_reg = sf * c_reg + si * tanhf(gv);
            float h = so * tanhf(c_reg);
            hbuf[((t + 1) & 1) * 16384 + m_g * 32 + eb] = h;
            yout[(size_t)(t * 32 + eb) * HD + m_g] = h;
        }
        __syncthreads();                          // all stores issued

        if (tid == 0) {
            __threadfence();                      // publish h (release)
            *((volatile unsigned*)&g_flags[bl]) = base + t + 1;
        }
        if (tid < 32) {
            unsigned target = base + t + 1;
            volatile unsigned* f = g_flags + tid * 4;
            for (;;) {
                int ok = ((int)(f[0] - target) >= 0) & ((int)(f[1] - target) >= 0) &
                         ((int)(f[2] - target) >= 0) & ((int)(f[3] - target) >= 0);
                if (__all_sync(0xFFFFFFFFu, ok)) break;
            }
            if (tid == 0) __threadfence();        // acquire
        }
        __syncthreads();
    }
    if (em) cbuf[m_g * 32 + eb] = c_reg;
}

// ---------------- launcher ----------------
extern "C" void kernel_launch(void* const* d_in, const int* in_sizes, int n_in,
                              void* d_out, int out_size) {
    const int*   x       = (const int*)  d_in[0];
    const int*   tgt     = (const int*)  d_in[1];
    const float* enc_emb = (const float*)d_in[2];
    const float* dec_emb = (const float*)d_in[3];
    const float* e0_Wih  = (const float*)d_in[4];
    const float* e0_Whh  = (const float*)d_in[5];
    const float* e0_b    = (const float*)d_in[6];
    const float* e1_Wih  = (const float*)d_in[7];
    const float* e1_Whh  = (const float*)d_in[8];
    const float* e1_b    = (const float*)d_in[9];
    const float* d0_Wih  = (const float*)d_in[10];
    const float* d0_Whh  = (const float*)d_in[11];
    const float* d0_b    = (const float*)d_in[12];
    const float* d1_Wih  = (const float*)d_in[13];
    const float* d1_Whh  = (const float*)d_in[14];
    const float* d1_b    = (const float*)d_in[15];
    const float* lin_W   = (const float*)d_in[16];
    const float* lin_b   = (const float*)d_in[17];
    float* out = (float*)d_out;

    float *xs, *pre, *y, *u2, *st;
    cudaGetSymbolAddress((void**)&xs,  g_xs);
    cudaGetSymbolAddress((void**)&pre, g_pre);
    cudaGetSymbolAddress((void**)&y,   g_y);
    cudaGetSymbolAddress((void**)&u2,  g_u2);
    cudaGetSymbolAddress((void**)&st,  g_state);

    cudaFuncSetAttribute(k_recur, cudaFuncAttributeMaxDynamicSharedMemorySize, RSMEM);
    cudaFuncSetAttribute(k_mmagemm<0>, cudaFuncAttributeMaxDynamicSharedMemorySize, GSMEM);
    cudaFuncSetAttribute(k_mmagemm<1>, cudaFuncAttributeMaxDynamicSharedMemorySize, GSMEM);

    dim3 gg(16, 16), gp(16, VOC / 128);

    k_zero<<<96, 256>>>();

    // encoder
    k_embed<<<M2, 128>>>(x, tgt, enc_emb, xs, 0);
    k_mmagemm<0><<<gg, 256, GSMEM>>>(xs, e0_Wih, e0_b, pre, G4);
    k_recur<<<RB, 256, RSMEM>>>(pre, e0_Whh, st + OFF_H0, st + OFF_C0, y);
    k_mmagemm<0><<<gg, 256, GSMEM>>>(y, e1_Wih, e1_b, pre, G4);
    k_recur<<<RB, 256, RSMEM>>>(pre, e1_Whh, st + OFF_H1, st + OFF_C1, u2);

    // decoder
    k_embed<<<M2, 128>>>(x, tgt, dec_emb, xs, 1);
    k_mmagemm<0><<<gg, 256, GSMEM>>>(xs, d0_Wih, d0_b, pre, G4);
    k_recur<<<RB, 256, RSMEM>>>(pre, d0_Whh, st + OFF_H0, st + OFF_C0, y);
    k_mmagemm<0><<<gg, 256, GSMEM>>>(y, d1_Wih, d1_b, pre, G4);
    k_recur<<<RB, 256, RSMEM>>>(pre, d1_Whh, st + OFF_H1, st + OFF_C1, u2);

    // projection
    k_mmagemm<1><<<gp, 256, GSMEM>>>(u2, lin_W, lin_b, out, VOC);
}

// round 5
// speedup vs baseline: 1.4733x; 1.0774x over previous
#include <cuda_runtime.h>
#include <cuda_bf16.h>
#include <math.h>
#include <stdint.h>

#define BSZ   32
#define TLEN  64
#define ED    512
#define HD    512
#define G4    2048
#define M2    2048
#define VOC   32000
#define RB    128

// ---------------- scratch (device globals; no allocation) ----------------
__device__ float g_xs [M2 * ED];
__device__ float g_pre[M2 * G4];
__device__ float g_y  [M2 * HD];
__device__ float g_u2 [M2 * HD];
__device__ float g_state[98304];
#define OFF_H0 0
#define OFF_C0 32768
#define OFF_H1 49152
#define OFF_C1 81920

__device__ unsigned g_flags[RB];   // monotonic per-block step counters

// ================= helpers =================
__device__ __forceinline__ uint32_t smem_u32(const void* p) {
    uint32_t a;
    asm("{ .reg .u64 t; cvta.to.shared.u64 t, %1; cvt.u32.u64 %0, t; }" : "=r"(a) : "l"(p));
    return a;
}

#define LDMX4(r0, r1, r2, r3, a) \
    asm volatile("ldmatrix.sync.aligned.m8n8.x4.shared.b16 {%0,%1,%2,%3}, [%4];" \
        : "=r"(r0), "=r"(r1), "=r"(r2), "=r"(r3) : "r"(a))

#define STS128(a, r0, r1, r2, r3) \
    asm volatile("st.shared.v4.b32 [%0], {%1,%2,%3,%4};" \
        :: "r"(a), "r"(r0), "r"(r1), "r"(r2), "r"(r3) : "memory")

__device__ __forceinline__ void mma16816(float* d, const uint32_t* a, const uint32_t* b) {
    asm volatile("mma.sync.aligned.m16n8k16.row.col.f32.bf16.bf16.f32 "
        "{%0,%1,%2,%3},{%4,%5,%6,%7},{%8,%9},{%0,%1,%2,%3};"
        : "+f"(d[0]), "+f"(d[1]), "+f"(d[2]), "+f"(d[3])
        : "r"(a[0]), "r"(a[1]), "r"(a[2]), "r"(a[3]), "r"(b[0]), "r"(b[1]));
}

__device__ __forceinline__ void cvt_hilo(const float4* v, uint32_t* h, uint32_t* l) {
    #pragma unroll
    for (int i = 0; i < 4; i++) {
        float a0 = v[i].x, a1 = v[i].y, a2 = v[i].z, a3 = v[i].w;
        uint32_t h0, h1, l0, l1;
        asm("cvt.rn.bf16x2.f32 %0, %1, %2;" : "=r"(h0) : "f"(a1), "f"(a0));
        asm("cvt.rn.bf16x2.f32 %0, %1, %2;" : "=r"(h1) : "f"(a3), "f"(a2));
        float r0 = a0 - __uint_as_float(h0 << 16);
        float r1 = a1 - __uint_as_float(h0 & 0xFFFF0000u);
        float r2 = a2 - __uint_as_float(h1 << 16);
        float r3 = a3 - __uint_as_float(h1 & 0xFFFF0000u);
        asm("cvt.rn.bf16x2.f32 %0, %1, %2;" : "=r"(l0) : "f"(r1), "f"(r0));
        asm("cvt.rn.bf16x2.f32 %0, %1, %2;" : "=r"(l1) : "f"(r3), "f"(r2));
        h[2*i] = h0; h[2*i+1] = h1; l[2*i] = l0; l[2*i+1] = l1;
    }
}

// ================= split-bf16 HMMA GEMM (unchanged, known-good) ====
#define PADK   40
#define T_BH   20480
#define STAGE  40960
#define GSMEM  81920

__device__ __forceinline__ void stage_store(uint32_t base, const float4* v) {
    uint32_t h[8], l[8];
    cvt_hilo(v, h, l);
    STS128(base,              h[0], h[1], h[2], h[3]);
    STS128(base + 16,         h[4], h[5], h[6], h[7]);
    STS128(base + 10240,      l[0], l[1], l[2], l[3]);
    STS128(base + 10240 + 16, l[4], l[5], l[6], l[7]);
}

template<int PERM>
__global__ void __launch_bounds__(256, 1)
k_mmagemm(const float* __restrict__ X, const float* __restrict__ W,
          const float* __restrict__ bias, float* __restrict__ C, int ldc) {
    extern __shared__ char smx[];
    uint32_t sb = smem_u32(smx);
    int tid = threadIdx.x, lid = tid & 31, wid = tid >> 5;
    int wm = wid >> 2, wn = wid & 3;
    int rb = blockIdx.x * 128, cb = blockIdx.y * 128;

    int r = tid >> 1, kh = (tid & 1) * 16;
    const float4* xp = (const float4*)(X + (size_t)(rb + r) * 512 + kh);
    const float4* wp = (const float4*)(W + (size_t)(cb + r) * 512 + kh);
    uint32_t stb = sb + (uint32_t)(r * PADK + kh) * 2;

    float4 xr[4], wr[4];
    #pragma unroll
    for (int i = 0; i < 4; i++) { xr[i] = xp[i]; wr[i] = wp[i]; }
    stage_store(stb, xr);
    stage_store(stb + T_BH, wr);
    __syncthreads();

    uint32_t abase = sb + (uint32_t)((wm * 64 + (lid & 15)) * PADK + (lid >> 4) * 8) * 2;
    uint32_t bbase = sb + T_BH + (uint32_t)((wn * 32 + (lid & 15)) * PADK + (lid >> 4) * 8) * 2;

    float acc[4][4][4] = {};

    for (int c = 0; c < 16; c++) {
        if (c < 15) {
            #pragma unroll
            for (int i = 0; i < 4; i++) { xr[i] = xp[(c + 1) * 8 + i]; wr[i] = wp[(c + 1) * 8 + i]; }
        }
        uint32_t so = (uint32_t)(c & 1) * STAGE;
        #pragma unroll
        for (int ks = 0; ks < 2; ks++) {
            uint32_t ah[4][4], al[4][4], bh[4][2], bl[4][2];
            #pragma unroll
            for (int ma = 0; ma < 4; ma++) {
                uint32_t ad = abase + so + (uint32_t)(ma * 16 * PADK * 2 + ks * 32);
                LDMX4(ah[ma][0], ah[ma][1], ah[ma][2], ah[ma][3], ad);
                LDMX4(al[ma][0], al[ma][1], al[ma][2], al[ma][3], ad + 10240);
            }
            #pragma unroll
            for (int p = 0; p < 2; p++) {
                uint32_t bd = bbase + so + (uint32_t)(p * 16 * PADK * 2 + ks * 32);
                uint32_t m0, m1, m2, m3;
                LDMX4(m0, m1, m2, m3, bd);
                bh[2*p][0] = m0; bh[2*p][1] = m2; bh[2*p+1][0] = m1; bh[2*p+1][1] = m3;
                LDMX4(m0, m1, m2, m3, bd + 10240);
                bl[2*p][0] = m0; bl[2*p][1] = m2; bl[2*p+1][0] = m1; bl[2*p+1][1] = m3;
            }
            #pragma unroll
            for (int ma = 0; ma < 4; ma++)
                #pragma unroll
                for (int na = 0; na < 4; na++) {
                    mma16816(acc[ma][na], ah[ma], bh[na]);
                    mma16816(acc[ma][na], ah[ma], bl[na]);
                    mma16816(acc[ma][na], al[ma], bh[na]);
                }
        }
        if (c < 15) {
            uint32_t st2 = stb + (uint32_t)((c + 1) & 1) * STAGE;
            stage_store(st2, xr);
            stage_store(st2 + T_BH, wr);
        }
        __syncthreads();
    }

    #pragma unroll
    for (int ma = 0; ma < 4; ma++) {
        int m  = rb + wm * 64 + ma * 16 + (lid >> 2);
        int m2 = m + 8;
        size_t ro0 = PERM ? (size_t)((m  & 31) * TLEN + (m  >> 5)) : (size_t)m;
        size_t ro1 = PERM ? (size_t)((m2 & 31) * TLEN + (m2 >> 5)) : (size_t)m2;
        #pragma unroll
        for (int na = 0; na < 4; na++) {
            int c0 = cb + wn * 32 + na * 8 + (lid & 3) * 2;
            float2 bv = *(const float2*)(bias + c0);
            float* a = acc[ma][na];
            *(float2*)(C + ro0 * (size_t)ldc + c0) = make_float2(a[0] + bv.x, a[1] + bv.y);
            *(float2*)(C + ro1 * (size_t)ldc + c0) = make_float2(a[2] + bv.x, a[3] + bv.y);
        }
    }
}

// ---------------- zero state ----------------
__global__ void k_zero() {
    int i = blockIdx.x * 256 + threadIdx.x;
    ((float4*)g_state)[i] = make_float4(0.f, 0.f, 0.f, 0.f);
}

// ---------------- embedding gather ----------------
__global__ void k_embed(const int* __restrict__ toks, const int* __restrict__ tgt,
                        const float* __restrict__ emb, float* __restrict__ xs, int dec) {
    int row = blockIdx.x;
    int t = row >> 5, b = row & 31;
    int tok;
    if (dec) tok = (t == 0) ? 1 : tgt[b * TLEN + t - 1];
    else     tok = toks[b * TLEN + t];
    const float4* src = (const float4*)(emb + (size_t)tok * ED);
    float4*       dst = (float4*)(xs + (size_t)row * ED);
    dst[threadIdx.x] = src[threadIdx.x];
}

// ================= persistent recurrence v3 =================
// 128 blocks x 256 threads. Thread = (row r 0..15, K-slice ks 0..15);
// warp = 16 rows x 2 slices -> h LDS are 16-lane broadcasts.
// W slice (32 floats) in registers for all 64 steps; acc[32] over batches.
// K-split partials reduced via padded smem; release/acquire flag barrier.
#define HSLICE 1032                       // floats per K-slice (32*32 + 8 pad)
#define P_STR  20                         // partials row stride (16 + 4 pad)
#define SM_PART 16512
#define SM_GATE (16512 + 10240)
#define RSMEM  ((16512 + 10240 + 512) * 4)

__global__ void __launch_bounds__(256, 1)
k_recur(const float* __restrict__ pre, const float* __restrict__ Whh,
        float* __restrict__ hbuf, float* __restrict__ cbuf,
        float* __restrict__ yout) {
    extern __shared__ float sm[];
    float* h_sm = sm;                      // [16][HSLICE]
    float* part = sm + SM_PART;            // [512][P_STR]
    float* gate = sm + SM_GATE;            // [512]

    int tid = threadIdx.x, bl = blockIdx.x;
    int w = tid >> 5, l = tid & 31;
    int ks = w * 2 + (l >> 4);             // K-slice 0..15
    int r  = l & 15;                       // gate row 0..15
    int col = (ks + r) & 15;               // XOR-rotated partial column

    // W slice in registers (step-invariant)
    int j = (r >> 2) * 512 + bl * 4 + (r & 3);
    float4 wreg[8];
    const float4* wsrc = (const float4*)(Whh + (size_t)j * 512 + ks * 32);
    #pragma unroll
    for (int i = 0; i < 8; i++) wreg[i] = wsrc[i];

    // reduction assignment: thread reduces outputs o0 = tid, o1 = tid+256
    int o0 = tid, o1 = tid + 256;
    int r0 = o0 >> 5, b0 = o0 & 31, r1 = o1 >> 5, b1 = o1 & 31;
    int j0 = (r0 >> 2) * 512 + bl * 4 + (r0 & 3);
    int j1 = (r1 >> 2) * 512 + bl * 4 + (r1 & 3);

    unsigned base = *((volatile unsigned*)&g_flags[bl]);

    int em = tid < 128;
    int m_l = (tid >> 5) & 3, eb = tid & 31;
    int m_g = bl * 4 + m_l;
    float c_reg = em ? cbuf[m_g * 32 + eb] : 0.f;

    for (int t = 0; t < TLEN; t++) {
        // prefetch pre operands (independent of h)
        float pp0 = pre[(size_t)(t * 32 + b0) * G4 + j0];
        float pp1 = pre[(size_t)(t * 32 + b1) * G4 + j1];

        // stage h(t) into K-slice layout
        const float4* hsrc = (const float4*)(hbuf + (t & 1) * 16384);
        #pragma unroll
        for (int i = 0; i < 16; i++) {
            int lin = tid + i * 256;
            float4 v = __ldcg(hsrc + lin);
            int k = lin >> 3, b4 = lin & 7;
            *(float4*)(h_sm + (k >> 5) * HSLICE + (k & 31) * 32 + b4 * 4) = v;
        }
        __syncthreads();

        // partial GEMM: this thread's row x K-slice over all 32 batches
        float acc[32];
        #pragma unroll
        for (int i = 0; i < 32; i++) acc[i] = 0.f;
        const float4* hq = (const float4*)(h_sm + ks * HSLICE);
        const float*  wf = (const float*)wreg;
        #pragma unroll 4
        for (int kl = 0; kl < 32; kl++) {
            float wv = wf[kl];
            #pragma unroll
            for (int q = 0; q < 8; q++) {
                float4 h4 = hq[kl * 8 + q];
                acc[q*4+0] = fmaf(wv, h4.x, acc[q*4+0]);
                acc[q*4+1] = fmaf(wv, h4.y, acc[q*4+1]);
                acc[q*4+2] = fmaf(wv, h4.z, acc[q*4+2]);
                acc[q*4+3] = fmaf(wv, h4.w, acc[q*4+3]);
            }
        }
        // scatter partials (XOR column to dodge bank conflicts)
        #pragma unroll
        for (int b = 0; b < 32; b++)
            part[(r * 32 + b) * P_STR + col] = acc[b];
        __syncthreads();

        // reduce 16 partials -> gate preactivation (+ input-path pre)
        {
            const float4* p0 = (const float4*)(part + o0 * P_STR);
            const float4* p1 = (const float4*)(part + o1 * P_STR);
            float4 s0 = p0[0], s1 = p1[0];
            #pragma unroll
            for (int c = 1; c < 4; c++) {
                float4 a = p0[c], b = p1[c];
                s0.x += a.x; s0.y += a.y; s0.z += a.z; s0.w += a.w;
                s1.x += b.x; s1.y += b.y; s1.z += b.z; s1.w += b.w;
            }
            gate[o0] = pp0 + s0.x + s0.y + s0.z + s0.w;
            gate[o1] = pp1 + s1.x + s1.y + s1.z + s1.w;
        }
        __syncthreads();

        if (em) {
            float iv = gate[(0  + m_l) * 32 + eb];
            float fv = gate[(4  + m_l) * 32 + eb];
            float gv = gate[(8  + m_l) * 32 + eb];
            float ov = gate[(12 + m_l) * 32 + eb];
            float si = 1.f / (1.f + expf(-iv));
            float sf = 1.f / (1.f + expf(-fv));
            float so = 1.f / (1.f + expf(-ov));
            c_reg = sf * c_reg + si * tanhf(gv);
            float h = so * tanhf(c_reg);
            hbuf[((t + 1) & 1) * 16384 + m_g * 32 + eb] = h;
            yout[(size_t)(t * 32 + eb) * HD + m_g] = h;
        }
        __syncthreads();                   // all h stores issued block-wide

        if (tid == 0)
            asm volatile("st.release.gpu.global.u32 [%0], %1;"
                :: "l"(g_flags + bl), "r"(base + t + 1) : "memory");
        if (tid < 32) {
            unsigned tg = base + t + 1;
            const unsigned* f = g_flags + tid * 4;
            for (;;) {
                unsigned v0, v1, v2, v3;
                asm volatile("ld.acquire.gpu.global.u32 %0, [%1];" : "=r"(v0) : "l"(f));
                asm volatile("ld.acquire.gpu.global.u32 %0, [%1];" : "=r"(v1) : "l"(f + 1));
                asm volatile("ld.acquire.gpu.global.u32 %0, [%1];" : "=r"(v2) : "l"(f + 2));
                asm volatile("ld.acquire.gpu.global.u32 %0, [%1];" : "=r"(v3) : "l"(f + 3));
                int ok = ((int)(v0 - tg) >= 0) & ((int)(v1 - tg) >= 0) &
                         ((int)(v2 - tg) >= 0) & ((int)(v3 - tg) >= 0);
                if (__all_sync(0xFFFFFFFFu, ok)) break;
            }
        }
        __syncthreads();
    }
    if (em) cbuf[m_g * 32 + eb] = c_reg;
}

// ---------------- launcher ----------------
extern "C" void kernel_launch(void* const* d_in, const int* in_sizes, int n_in,
                              void* d_out, int out_size) {
    const int*   x       = (const int*)  d_in[0];
    const int*   tgt     = (const int*)  d_in[1];
    const float* enc_emb = (const float*)d_in[2];
    const float* dec_emb = (const float*)d_in[3];
    const float* e0_Wih  = (const float*)d_in[4];
    const float* e0_Whh  = (const float*)d_in[5];
    const float* e0_b    = (const float*)d_in[6];
    const float* e1_Wih  = (const float*)d_in[7];
    const float* e1_Whh  = (const float*)d_in[8];
    const float* e1_b    = (const float*)d_in[9];
    const float* d0_Wih  = (const float*)d_in[10];
    const float* d0_Whh  = (const float*)d_in[11];
    const float* d0_b    = (const float*)d_in[12];
    const float* d1_Wih  = (const float*)d_in[13];
    const float* d1_Whh  = (const float*)d_in[14];
    const float* d1_b    = (const float*)d_in[15];
    const float* lin_W   = (const float*)d_in[16];
    const float* lin_b   = (const float*)d_in[17];
    float* out = (float*)d_out;

    float *xs, *pre, *y, *u2, *st;
    cudaGetSymbolAddress((void**)&xs,  g_xs);
    cudaGetSymbolAddress((void**)&pre, g_pre);
    cudaGetSymbolAddress((void**)&y,   g_y);
    cudaGetSymbolAddress((void**)&u2,  g_u2);
    cudaGetSymbolAddress((void**)&st,  g_state);

    cudaFuncSetAttribute(k_recur, cudaFuncAttributeMaxDynamicSharedMemorySize, RSMEM);
    cudaFuncSetAttribute(k_mmagemm<0>, cudaFuncAttributeMaxDynamicSharedMemorySize, GSMEM);
    cudaFuncSetAttribute(k_mmagemm<1>, cudaFuncAttributeMaxDynamicSharedMemorySize, GSMEM);

    dim3 gg(16, 16), gp(16, VOC / 128);

    k_zero<<<96, 256>>>();

    // encoder
    k_embed<<<M2, 128>>>(x, tgt, enc_emb, xs, 0);
    k_mmagemm<0><<<gg, 256, GSMEM>>>(xs, e0_Wih, e0_b, pre, G4);
    k_recur<<<RB, 256, RSMEM>>>(pre, e0_Whh, st + OFF_H0, st + OFF_C0, y);
    k_mmagemm<0><<<gg, 256, GSMEM>>>(y, e1_Wih, e1_b, pre, G4);
    k_recur<<<RB, 256, RSMEM>>>(pre, e1_Whh, st + OFF_H1, st + OFF_C1, u2);

    // decoder
    k_embed<<<M2, 128>>>(x, tgt, dec_emb, xs, 1);
    k_mmagemm<0><<<gg, 256, GSMEM>>>(xs, d0_Wih, d0_b, pre, G4);
    k_recur<<<RB, 256, RSMEM>>>(pre, d0_Whh, st + OFF_H0, st + OFF_C0, y);
    k_mmagemm<0><<<gg, 256, GSMEM>>>(y, d1_Wih, d1_b, pre, G4);
    k_recur<<<RB, 256, RSMEM>>>(pre, d1_Whh, st + OFF_H1, st + OFF_C1, u2);

    // projection
    k_mmagemm<1><<<gp, 256, GSMEM>>>(u2, lin_W, lin_b, out, VOC);
}